// round 16
// baseline (speedup 1.0000x reference)
#include <cuda_runtime.h>
#include <cfloat>

#define B_    128
#define K_    16
#define V_    50257
#define T_    20
#define H_    512
#define NROW  2048
#define VPADW 12568          // u32 words per batch (16B-aligned per batch)
#define VH    25128          // half split (divisible by 4)

#define O0 0
#define O1 (B_ * T_ * K_)
#define O2 (2 * B_ * T_ * K_)
#define O3 (2 * B_ * T_ * K_ + B_ * K_)

#define BUFCAP   768         // raw survivors per half (mean ~156)
#define THR_INIT (-8.8f)     // heuristic; exact fallback guards correctness
#define SMALLCAP 160

__device__ unsigned int       g_cnt32[B_ * VPADW];  // packed uint8 diversity counts
__device__ unsigned long long g_key[NROW * 2 * 16]; // per-(row,half) top-16 keys
__device__ int                g_flag[B_];           // per-batch counts-ready flag
__device__ int                g_done;               // completion counter (self-reset)

// ---------------------------------------------------------------------------
__device__ __forceinline__ unsigned ford(float v) {
    unsigned u = __float_as_uint(v);
    return (u & 0x80000000u) ? ~u : (u | 0x80000000u);
}
__device__ __forceinline__ float funord(unsigned u) {
    return __uint_as_float((u & 0x80000000u) ? (u ^ 0x80000000u) : ~u);
}
// per-row key: value desc primary, token asc secondary (larger key = better)
__device__ __forceinline__ unsigned long long mkkey(float v, int tok) {
    return ((unsigned long long)ford(v) << 32) | (unsigned)(~(unsigned)tok);
}
__device__ __forceinline__ int keytok(unsigned long long k) {
    return (int)(~(unsigned)k);
}

__device__ __forceinline__ int blk_sum(int c, int* s_ws) {
    int tid = threadIdx.x;
    c = (int)__reduce_add_sync(0xffffffffu, (unsigned)c);
    if ((tid & 31) == 0) s_ws[tid >> 5] = c;
    __syncthreads();
    int t = s_ws[0] + s_ws[1] + s_ws[2] + s_ws[3] + s_ws[4] + s_ws[5] + s_ws[6] + s_ws[7];
    __syncthreads();
    return t;
}

// int64-vs-int32 detect for token arrays (all tokens in [0,V) iff int64)
__device__ __forceinline__ int detect64(const void* p) {
    const long long* q = (const long long*)p;
    int ok = 1;
    for (int i = 0; i < 8; i++) { long long v = q[i]; if (v < 0 || v >= V_) ok = 0; }
    return ok;
}

// ---------------------------------------------------------------------------
// RAW filter only — no diversity/EOS work in the hot loop (both only lower
// values, so raw >= thr is a necessary condition; epilogue applies them).
__device__ __forceinline__ void pquad(float4 A, int fidx, float thr,
        unsigned long long* s_buf, int* s_cnt, int* s_ovf) {
    float m = fmaxf(fmaxf(A.x, A.y), fmaxf(A.z, A.w));
    if (m < thr) return;
    if (A.x >= thr) { int p = atomicAdd(s_cnt, 1); if (p < BUFCAP) s_buf[p] = mkkey(A.x, fidx);     else *s_ovf = 1; }
    if (A.y >= thr) { int p = atomicAdd(s_cnt, 1); if (p < BUFCAP) s_buf[p] = mkkey(A.y, fidx + 1); else *s_ovf = 1; }
    if (A.z >= thr) { int p = atomicAdd(s_cnt, 1); if (p < BUFCAP) s_buf[p] = mkkey(A.z, fidx + 2); else *s_ovf = 1; }
    if (A.w >= thr) { int p = atomicAdd(s_cnt, 1); if (p < BUFCAP) s_buf[p] = mkkey(A.w, fidx + 3); else *s_ovf = 1; }
}

// per-(row,half) exact top-16 of aug = lp - 0.5*count (EOS -1000 at V-1).
// Blocks with blockIdx%32==0 build their batch's diversity counts first and
// set g_flag[b]; epilogues spin on the flag (prep block always has the lowest
// blockIdx of its batch and never waits -> no deadlock).
__global__ void __launch_bounds__(256) k_topk(const float* __restrict__ logprobs,
                                              const void* __restrict__ prev) {
    __shared__ unsigned long long s_buf[BUFCAP];    // 6 KB
    __shared__ unsigned long long s_b2[256];        // 2 KB
    __shared__ int s_ws[8];
    __shared__ int s_cnt, s_ovf, s_cnt2, s_is64;

    int tid = threadIdx.x;
    int row = blockIdx.x >> 1;
    int h   = blockIdx.x & 1;
    int b = row >> 4;
    const float* __restrict__ lp = logprobs + (size_t)row * V_;
    const unsigned char* __restrict__ cb =
        (const unsigned char*)g_cnt32 + (size_t)b * (VPADW * 4);

    int s = h ? VH : 0;
    int e = h ? V_ : VH;
    int off0 = (int)(((size_t)row * V_ + s) & 3);
    int pad = (4 - off0) & 3;                       // scalar prologue length
    const float4* __restrict__ lp4 = (const float4*)(lp + s + pad);

    if (tid == 0) { s_cnt = 0; s_ovf = 0; }

    // ---- prep (one block per batch): zero + build counts, set flag ----
    if ((blockIdx.x & 31) == 0) {
        if (tid == 0) s_is64 = detect64(prev);
        __syncthreads();
        unsigned int* c = g_cnt32 + (size_t)b * VPADW;
        uint4* c4 = (uint4*)c;                      // VPADW%4==0, 16B-aligned
        const uint4 z = make_uint4(0u, 0u, 0u, 0u);
        for (int i = tid; i < VPADW / 4; i += 256) c4[i] = z;
        __syncthreads();
        long long v = s_is64 ? ((const long long*)prev)[b * 256 + tid]
                             : (long long)((const int*)prev)[b * 256 + tid];
        int vi = (int)v;
        atomicAdd(&c[vi >> 2], 1u << ((vi & 3) * 8));
        __threadfence();
        __syncthreads();
        if (tid == 0) atomicExch(&g_flag[b], 1);
    }
    __syncthreads();

    const float thr = THR_INIT;

    if (tid < pad) {                                // prologue
        float v = lp[s + tid];
        if (v >= thr) {
            int p = atomicAdd(&s_cnt, 1);
            if (p < BUFCAP) s_buf[p] = mkkey(v, s + tid); else s_ovf = 1;
        }
    }

    // warp-autonomous barrier-free stream
    int wid = tid >> 5, lane = tid & 31;
    int quads_total = (e - s - pad) >> 2;
    int per_w = quads_total >> 3;
    int qi = wid * per_w;
    int nq = (wid == 7) ? (quads_total - 7 * per_w) : per_w;
    int qend = qi + nq;

    for (; qi + 256 <= qend; qi += 256) {
        float4 A[8];
#pragma unroll
        for (int j = 0; j < 8; j++) A[j] = __ldcs(&lp4[qi + j * 32 + lane]);
#pragma unroll
        for (int j = 0; j < 8; j++)
            pquad(A[j], s + pad + 4 * (qi + j * 32 + lane), thr, s_buf, &s_cnt, &s_ovf);
    }
    for (; qi + 32 <= qend; qi += 32) {
        float4 A = __ldcs(&lp4[qi + lane]);
        pquad(A, s + pad + 4 * (qi + lane), thr, s_buf, &s_cnt, &s_ovf);
    }
    if (qi + lane < qend) {
        float4 A = __ldcs(&lp4[qi + lane]);
        pquad(A, s + pad + 4 * (qi + lane), thr, s_buf, &s_cnt, &s_ovf);
    }
    if (wid == 7) {                                 // scalar remainder [.., e)
        int rstart = s + pad + 4 * quads_total;
        for (int idx = rstart + lane; idx < e; idx += 32) {
            float v = lp[idx];
            if (v >= thr) {
                int p = atomicAdd(&s_cnt, 1);
                if (p < BUFCAP) s_buf[p] = mkkey(v, idx); else s_ovf = 1;
            }
        }
    }
    __syncthreads();

    // ---- wait for this batch's counts (prep finished ~20us ago normally) ----
    if (tid == 0) {
        while (atomicAdd(&g_flag[b], 0) == 0) { }
    }
    __syncthreads();

    // epilogue: batch-convert raw -> aug (EOS + diversity applied here)
    int n = s_cnt; if (n > BUFCAP) n = BUFCAP;
    int cgood = 0;
    for (int i = tid; i < n; i += 256) {
        unsigned long long k = s_buf[i];
        int tok = keytok(k);
        float v = funord((unsigned)(k >> 32));
        if (tok == V_ - 1) v -= 1000.0f;
        float a = v - 0.5f * (float)cb[tok];
        s_buf[i] = mkkey(a, tok);
        cgood += (a >= thr);
    }
    int good = blk_sum(cgood, s_ws);

    // cold exact fallback over this half (data-independent correctness)
    if (s_ovf || good < 16) {
        __syncthreads();
        if (tid == 0) s_cnt = 0;
        __syncthreads();
        float flo = -3.0e38f, fhi = 1.0f;
        for (int it = 0; it < 48; it++) {
            float mid = 0.5f * (flo + fhi);
            int c = 0;
            for (int idx = s + tid; idx < e; idx += 256) {
                float v = lp[idx];
                if (idx == V_ - 1) v -= 1000.0f;
                c += ((v - 0.5f * (float)cb[idx]) >= mid);
            }
            int tot = blk_sum(c, s_ws);
            if (tot >= 16) { flo = mid; if (tot <= BUFCAP / 2) break; }
            else fhi = mid;
        }
        for (int idx = s + tid; idx < e; idx += 256) {
            float v = lp[idx];
            if (idx == V_ - 1) v -= 1000.0f;
            float a = v - 0.5f * (float)cb[idx];
            if (a >= flo) {
                int p = atomicAdd(&s_cnt, 1);
                if (p < BUFCAP) s_buf[p] = mkkey(a, idx);
            }
        }
        __syncthreads();
        n = s_cnt; if (n > BUFCAP) n = BUFCAP;
    } else {
        __syncthreads();
    }

    // narrow if large, then exact rank selection over unique u64 keys
    unsigned long long* sel = s_buf;
    int nsel = n;
    if (n > 512) {
        float rlo = -3.0e38f, rhi = 1.0f;
        int cnt_at_rlo = n;
        for (int it = 0; it < 24; it++) {
            float mid = 0.5f * (rlo + rhi);
            unsigned long long km = ((unsigned long long)ford(mid)) << 32;
            int c = 0;
            for (int p = tid; p < n; p += 256) c += (s_buf[p] >= km);
            int tot = blk_sum(c, s_ws);
            if (tot >= 16) { rlo = mid; cnt_at_rlo = tot; if (tot <= 96) break; }
            else rhi = mid;
        }
        if (cnt_at_rlo <= 256) {
            if (tid == 0) s_cnt2 = 0;
            __syncthreads();
            unsigned long long km = ((unsigned long long)ford(rlo)) << 32;
            for (int p = tid; p < n; p += 256) {
                unsigned long long k = s_buf[p];
                if (k >= km) { int q = atomicAdd(&s_cnt2, 1); if (q < 256) s_b2[q] = k; }
            }
            __syncthreads();
            sel = s_b2;
            nsel = s_cnt2; if (nsel > 256) nsel = 256;
        }
    }
    for (int i = tid; i < nsel; i += 256) {
        unsigned long long k = sel[i];
        int r = 0;
        for (int p = 0; p < nsel; p++) r += (sel[p] > k);
        if (r < 16) g_key[(size_t)blockIdx.x * 16 + r] = k;
    }

    // ---- last block to finish resets flags + counter (replay-safe) ----
    __syncthreads();
    if (tid == 0) {
        __threadfence();
        int old = atomicAdd(&g_done, 1);
        if (old == NROW * 2 - 1) {
            for (int i = 0; i < B_; i++) atomicExch(&g_flag[i], 0);
            atomicExch(&g_done, 0);
        }
    }
}

// ---------------------------------------------------------------------------
// per-batch: global top-16 over 512 candidates (head-bound + small rank),
// history rewrite, AND fused state gather (64 rows of H=512 per batch).
__global__ void __launch_bounds__(256) k_select(
        const float* __restrict__ logprobs,
        const void*  __restrict__ beam_seq,
        const float* __restrict__ beam_lps,
        const float* __restrict__ sums,
        const void*  __restrict__ tin,
        const float* __restrict__ state,
        float* __restrict__ out) {
    __shared__ unsigned long long s_k2[512];
    __shared__ unsigned long long s_small[SMALLCAP];
    __shared__ unsigned long long s_T;
    __shared__ float s_sums[16];
    __shared__ int s_nc, s_is64;
    __shared__ int s_q[16], s_token[16];
    __shared__ float s_r[16];

    int b = blockIdx.x, tid = threadIdx.x;
    if (tid < 16) s_sums[tid] = sums[b * 16 + tid];
    if (tid == 0) { s_nc = 0; s_is64 = detect64(beam_seq); }
    __syncthreads();

    unsigned long long my[2];
#pragma unroll
    for (int j = 0; j < 2; j++) {
        int i = tid + j * 256;                 // key index in [0,512)
        unsigned long long k = g_key[(size_t)b * 512 + i];
        int q = i >> 5;                        // list = i>>4, q = list>>1
        int tok = keytok(k);
        float augv = funord((unsigned)(k >> 32));
        float comb = augv + s_sums[q];
        // global key: comb desc, q asc, token asc == jax flat-index tie-break
        unsigned long long k2 = ((unsigned long long)ford(comb) << 32)
                              | ((unsigned)(15 - q) << 17)
                              | (unsigned)(131071 - tok);
        s_k2[i] = k2;
        my[j] = k2;
    }
    __syncthreads();

    // warp 0: T = 16th largest of the 32 list heads (keys unique)
    if (tid < 32) {
        unsigned long long cur = s_k2[tid * 16];
        unsigned long long T = 0ull;
        for (int r = 0; r < 16; r++) {
            unsigned long long m2 = cur;
            for (int off = 16; off; off >>= 1) {
                unsigned long long o = __shfl_xor_sync(0xffffffffu, m2, off);
                if (o > m2) m2 = o;
            }
            T = m2;
            if (cur == m2) cur = 0ull;
        }
        if (tid == 0) s_T = T;
    }
    __syncthreads();

    unsigned long long T = s_T;
#pragma unroll
    for (int j = 0; j < 2; j++) {
        if (my[j] >= T) {
            int p = atomicAdd(&s_nc, 1);
            if (p < SMALLCAP) s_small[p] = my[j];
        }
    }
    __syncthreads();
    int m = s_nc;

    if (m <= SMALLCAP) {
        for (int i = tid; i < m; i += 256) {
            unsigned long long k2 = s_small[i];
            int r = 0;
            for (int p = 0; p < m; p++) r += (s_small[p] > k2);
            if (r < 16) {
                int q = 15 - (int)((k2 >> 17) & 15u);
                int tok = 131071 - (int)(k2 & 0x1FFFFu);
                float comb = funord((unsigned)(k2 >> 32));
                float rr = logprobs[(size_t)(b * 16 + q) * V_ + tok];
                if (tok == V_ - 1) rr -= 1000.0f;
                s_q[r] = q; s_token[r] = tok; s_r[r] = rr;
                out[O2 + b * 16 + r] = comb;
            }
        }
    } else {                                   // fallback: rank all 512
#pragma unroll
        for (int j = 0; j < 2; j++) {
            unsigned long long k2 = my[j];
            int r = 0;
            for (int p = 0; p < 512; p++) r += (s_k2[p] > k2);
            if (r < 16) {
                int q = 15 - (int)((k2 >> 17) & 15u);
                int tok = 131071 - (int)(k2 & 0x1FFFFu);
                float comb = funord((unsigned)(k2 >> 32));
                float rr = logprobs[(size_t)(b * 16 + q) * V_ + tok];
                if (tok == V_ - 1) rr -= 1000.0f;
                s_q[r] = q; s_token[r] = tok; s_r[r] = rr;
                out[O2 + b * 16 + r] = comb;
            }
        }
    }
    __syncthreads();

    int is64 = s_is64;
    int t = ((const int*)tin)[0];
    for (int idx = tid; idx < T_ * K_; idx += 256) {
        int rowi = idx >> 4, k2i = idx & 15;
        float sv, lv;
        if (rowi == t) {
            sv = (float)s_token[k2i];
            lv = s_r[k2i];
        } else {
            int kk = (rowi < t) ? s_q[k2i] : k2i;
            int off = (b * T_ + rowi) * K_ + kk;
            sv = is64 ? (float)((const long long*)beam_seq)[off]
                      : (float)((const int*)beam_seq)[off];
            lv = beam_lps[off];
        }
        out[O0 + b * (T_ * K_) + idx] = sv;
        out[O1 + b * (T_ * K_) + idx] = lv;
    }

    // fused state gather: 64 rows (4 sl x 16 k) x 512 floats for this batch
    for (int idx = tid; idx < 8192; idx += 1024) {
#pragma unroll
        for (int j = 0; j < 4; j++) {
            int ii = idx + j * 256;
            int rowi = ii >> 7;                  // [0,64): sl*16 + k
            int l = ii & 127;
            int sl = rowi >> 4, k = rowi & 15;
            int q = s_q[k];
            const float4* src = (const float4*)(state + ((((size_t)sl * B_) + b) * K_ + q) * H_);
            float4*       dst = (float4*)(out + O3 + ((((size_t)sl * B_) + b) * K_ + k) * H_);
            dst[l] = src[l];
        }
    }
}

// ---------------------------------------------------------------------------
extern "C" void kernel_launch(void* const* d_in, const int* in_sizes, int n_in,
                              void* d_out, int out_size) {
    const float* logprobs = (const float*)d_in[0];
    const void*  beam_seq = d_in[1];
    const float* beam_lps = (const float*)d_in[2];
    const float* sums     = (const float*)d_in[3];
    const float* state    = (const float*)d_in[4];
    const void*  prev     = d_in[5];
    const void*  tin      = d_in[6];
    float* out = (float*)d_out;

    k_topk<<<NROW * 2, 256>>>(logprobs, prev);
    k_select<<<B_, 256>>>(logprobs, beam_seq, beam_lps, sums, tin, state, out);
}

// round 17
// speedup vs baseline: 1.0663x; 1.0663x over previous
#include <cuda_runtime.h>
#include <cfloat>

#define B_    128
#define K_    16
#define V_    50257
#define T_    20
#define H_    512
#define NROW  2048
#define VPADW 12568          // u32 words per batch
#define VH    25128          // half split (divisible by 4)

#define O0 0
#define O1 (B_ * T_ * K_)
#define O2 (2 * B_ * T_ * K_)
#define O3 (2 * B_ * T_ * K_ + B_ * K_)

#define BUFCAP   768         // raw survivors per half (mean ~156)
#define THR_INIT (-8.8f)     // heuristic; exact fallback guards correctness
#define SMALLCAP 160

// g_cnt32 invariant: all-zero at every launch boundary (zero-init at load;
// k_prep increments only prev-token words; k_select resets exactly those).
__device__ unsigned int       g_cnt32[B_ * VPADW];
__device__ unsigned long long g_key[NROW * 2 * 16]; // per-(row,half) top-16 keys
__device__ int                g_is64;

// ---------------------------------------------------------------------------
__device__ __forceinline__ unsigned ford(float v) {
    unsigned u = __float_as_uint(v);
    return (u & 0x80000000u) ? ~u : (u | 0x80000000u);
}
__device__ __forceinline__ float funord(unsigned u) {
    return __uint_as_float((u & 0x80000000u) ? (u ^ 0x80000000u) : ~u);
}
// per-row key: value desc primary, token asc secondary (larger key = better)
__device__ __forceinline__ unsigned long long mkkey(float v, int tok) {
    return ((unsigned long long)ford(v) << 32) | (unsigned)(~(unsigned)tok);
}
__device__ __forceinline__ int keytok(unsigned long long k) {
    return (int)(~(unsigned)k);
}

__device__ __forceinline__ int blk_sum(int c, int* s_ws) {
    int tid = threadIdx.x;
    c = (int)__reduce_add_sync(0xffffffffu, (unsigned)c);
    if ((tid & 31) == 0) s_ws[tid >> 5] = c;
    __syncthreads();
    int t = s_ws[0] + s_ws[1] + s_ws[2] + s_ws[3] + s_ws[4] + s_ws[5] + s_ws[6] + s_ws[7];
    __syncthreads();
    return t;
}

// int64-vs-int32 detect for token arrays (all tokens in [0,V) iff int64)
__device__ __forceinline__ int detect64(const void* p) {
    const long long* q = (const long long*)p;
    int ok = 1;
    for (int i = 0; i < 8; i++) { long long v = q[i]; if (v < 0 || v >= V_) ok = 0; }
    return ok;
}

// ---------------------------------------------------------------------------
// prep: dtype detect + atomic count build (NO zeroing — see invariant above)
__global__ void __launch_bounds__(256) k_prep(const void* __restrict__ prev,
                                              const void* __restrict__ beam_seq) {
    int b = blockIdx.x, tid = threadIdx.x;
    __shared__ int s_is64;
    if (tid == 0) {
        s_is64 = detect64(prev);
        if (b == 0) g_is64 = detect64(beam_seq);
    }
    __syncthreads();
    unsigned int* c = g_cnt32 + (size_t)b * VPADW;
    long long v = s_is64 ? ((const long long*)prev)[b * 256 + tid]
                         : (long long)((const int*)prev)[b * 256 + tid];
    int vi = (int)v;
    atomicAdd(&c[vi >> 2], 1u << ((vi & 3) * 8));
}

// ---------------------------------------------------------------------------
// RAW filter only — no diversity/EOS work in the hot loop (both only lower
// values, so raw >= thr is a necessary condition; epilogue applies them).
__device__ __forceinline__ void pquad(float4 A, int fidx, float thr,
        unsigned long long* s_buf, int* s_cnt, int* s_ovf) {
    float m = fmaxf(fmaxf(A.x, A.y), fmaxf(A.z, A.w));
    if (m < thr) return;
    if (A.x >= thr) { int p = atomicAdd(s_cnt, 1); if (p < BUFCAP) s_buf[p] = mkkey(A.x, fidx);     else *s_ovf = 1; }
    if (A.y >= thr) { int p = atomicAdd(s_cnt, 1); if (p < BUFCAP) s_buf[p] = mkkey(A.y, fidx + 1); else *s_ovf = 1; }
    if (A.z >= thr) { int p = atomicAdd(s_cnt, 1); if (p < BUFCAP) s_buf[p] = mkkey(A.z, fidx + 2); else *s_ovf = 1; }
    if (A.w >= thr) { int p = atomicAdd(s_cnt, 1); if (p < BUFCAP) s_buf[p] = mkkey(A.w, fidx + 3); else *s_ovf = 1; }
}

// per-(row,half) exact top-16 of aug = lp - 0.5*count (EOS -1000 at V-1)
__global__ void __launch_bounds__(256) k_topk(const float* __restrict__ logprobs) {
    __shared__ unsigned long long s_buf[BUFCAP];    // 6 KB
    __shared__ unsigned long long s_b2[256];        // 2 KB
    __shared__ int s_ws[8];
    __shared__ int s_cnt, s_ovf, s_cnt2;

    int tid = threadIdx.x;
    int row = blockIdx.x >> 1;
    int h   = blockIdx.x & 1;
    int b = row >> 4;
    const float* __restrict__ lp = logprobs + (size_t)row * V_;
    const unsigned char* __restrict__ cb =
        (const unsigned char*)g_cnt32 + (size_t)b * (VPADW * 4);

    int s = h ? VH : 0;
    int e = h ? V_ : VH;
    int off0 = (int)(((size_t)row * V_ + s) & 3);
    int pad = (4 - off0) & 3;                       // scalar prologue length
    const float4* __restrict__ lp4 = (const float4*)(lp + s + pad);

    if (tid == 0) { s_cnt = 0; s_ovf = 0; }
    __syncthreads();

    const float thr = THR_INIT;

    if (tid < pad) {                                // prologue
        float v = lp[s + tid];
        if (v >= thr) {
            int p = atomicAdd(&s_cnt, 1);
            if (p < BUFCAP) s_buf[p] = mkkey(v, s + tid); else s_ovf = 1;
        }
    }

    // warp-autonomous barrier-free stream
    int wid = tid >> 5, lane = tid & 31;
    int quads_total = (e - s - pad) >> 2;
    int per_w = quads_total >> 3;
    int qi = wid * per_w;
    int nq = (wid == 7) ? (quads_total - 7 * per_w) : per_w;
    int qend = qi + nq;

    for (; qi + 256 <= qend; qi += 256) {
        float4 A[8];
#pragma unroll
        for (int j = 0; j < 8; j++) A[j] = __ldcs(&lp4[qi + j * 32 + lane]);
#pragma unroll
        for (int j = 0; j < 8; j++)
            pquad(A[j], s + pad + 4 * (qi + j * 32 + lane), thr, s_buf, &s_cnt, &s_ovf);
    }
    for (; qi + 32 <= qend; qi += 32) {
        float4 A = __ldcs(&lp4[qi + lane]);
        pquad(A, s + pad + 4 * (qi + lane), thr, s_buf, &s_cnt, &s_ovf);
    }
    if (qi + lane < qend) {
        float4 A = __ldcs(&lp4[qi + lane]);
        pquad(A, s + pad + 4 * (qi + lane), thr, s_buf, &s_cnt, &s_ovf);
    }
    if (wid == 7) {                                 // scalar remainder [.., e)
        int rstart = s + pad + 4 * quads_total;
        for (int idx = rstart + lane; idx < e; idx += 32) {
            float v = lp[idx];
            if (v >= thr) {
                int p = atomicAdd(&s_cnt, 1);
                if (p < BUFCAP) s_buf[p] = mkkey(v, idx); else s_ovf = 1;
            }
        }
    }
    __syncthreads();

    // epilogue: batch-convert raw -> aug (EOS + diversity applied here)
    int n = s_cnt; if (n > BUFCAP) n = BUFCAP;
    int cgood = 0;
    for (int i = tid; i < n; i += 256) {
        unsigned long long k = s_buf[i];
        int tok = keytok(k);
        float v = funord((unsigned)(k >> 32));
        if (tok == V_ - 1) v -= 1000.0f;
        float a = v - 0.5f * (float)cb[tok];
        s_buf[i] = mkkey(a, tok);
        cgood += (a >= thr);
    }
    int good = blk_sum(cgood, s_ws);

    // cold exact fallback over this half (data-independent correctness)
    if (s_ovf || good < 16) {
        __syncthreads();
        if (tid == 0) s_cnt = 0;
        __syncthreads();
        float flo = -3.0e38f, fhi = 1.0f;
        for (int it = 0; it < 48; it++) {
            float mid = 0.5f * (flo + fhi);
            int c = 0;
            for (int idx = s + tid; idx < e; idx += 256) {
                float v = lp[idx];
                if (idx == V_ - 1) v -= 1000.0f;
                c += ((v - 0.5f * (float)cb[idx]) >= mid);
            }
            int tot = blk_sum(c, s_ws);
            if (tot >= 16) { flo = mid; if (tot <= BUFCAP / 2) break; }
            else fhi = mid;
        }
        for (int idx = s + tid; idx < e; idx += 256) {
            float v = lp[idx];
            if (idx == V_ - 1) v -= 1000.0f;
            float a = v - 0.5f * (float)cb[idx];
            if (a >= flo) {
                int p = atomicAdd(&s_cnt, 1);
                if (p < BUFCAP) s_buf[p] = mkkey(a, idx);
            }
        }
        __syncthreads();
        n = s_cnt; if (n > BUFCAP) n = BUFCAP;
    } else {
        __syncthreads();
    }

    // narrow if large, then exact rank selection over unique u64 keys
    unsigned long long* sel = s_buf;
    int nsel = n;
    if (n > 512) {
        float rlo = -3.0e38f, rhi = 1.0f;
        int cnt_at_rlo = n;
        for (int it = 0; it < 24; it++) {
            float mid = 0.5f * (rlo + rhi);
            unsigned long long km = ((unsigned long long)ford(mid)) << 32;
            int c = 0;
            for (int p = tid; p < n; p += 256) c += (s_buf[p] >= km);
            int tot = blk_sum(c, s_ws);
            if (tot >= 16) { rlo = mid; cnt_at_rlo = tot; if (tot <= 96) break; }
            else rhi = mid;
        }
        if (cnt_at_rlo <= 256) {
            if (tid == 0) s_cnt2 = 0;
            __syncthreads();
            unsigned long long km = ((unsigned long long)ford(rlo)) << 32;
            for (int p = tid; p < n; p += 256) {
                unsigned long long k = s_buf[p];
                if (k >= km) { int q = atomicAdd(&s_cnt2, 1); if (q < 256) s_b2[q] = k; }
            }
            __syncthreads();
            sel = s_b2;
            nsel = s_cnt2; if (nsel > 256) nsel = 256;
        }
    }
    for (int i = tid; i < nsel; i += 256) {
        unsigned long long k = sel[i];
        int r = 0;
        for (int p = 0; p < nsel; p++) r += (sel[p] > k);
        if (r < 16) g_key[(size_t)blockIdx.x * 16 + r] = k;
    }
}

// ---------------------------------------------------------------------------
// per-batch: global top-16 over 512 candidates (head-bound + small rank),
// history rewrite, fused state gather (deep ILP), and count-table reset.
__global__ void __launch_bounds__(256) k_select(
        const float* __restrict__ logprobs,
        const void*  __restrict__ beam_seq,
        const float* __restrict__ beam_lps,
        const float* __restrict__ sums,
        const void*  __restrict__ tin,
        const float* __restrict__ state,
        const void*  __restrict__ prev,
        float* __restrict__ out) {
    __shared__ unsigned long long s_k2[512];
    __shared__ unsigned long long s_small[SMALLCAP];
    __shared__ unsigned long long s_T;
    __shared__ float s_sums[16];
    __shared__ int s_nc, s_is64p;
    __shared__ int s_q[16], s_token[16];
    __shared__ float s_r[16];

    int b = blockIdx.x, tid = threadIdx.x;
    if (tid < 16) s_sums[tid] = sums[b * 16 + tid];
    if (tid == 0) { s_nc = 0; s_is64p = detect64(prev); }
    __syncthreads();

    unsigned long long my[2];
#pragma unroll
    for (int j = 0; j < 2; j++) {
        int i = tid + j * 256;                 // key index in [0,512)
        unsigned long long k = g_key[(size_t)b * 512 + i];
        int q = i >> 5;                        // list = i>>4, q = list>>1
        int tok = keytok(k);
        float augv = funord((unsigned)(k >> 32));
        float comb = augv + s_sums[q];
        // global key: comb desc, q asc, token asc == jax flat-index tie-break
        unsigned long long k2 = ((unsigned long long)ford(comb) << 32)
                              | ((unsigned)(15 - q) << 17)
                              | (unsigned)(131071 - tok);
        s_k2[i] = k2;
        my[j] = k2;
    }
    __syncthreads();

    // warp 0: T = 16th largest of the 32 list heads (keys unique)
    if (tid < 32) {
        unsigned long long cur = s_k2[tid * 16];
        unsigned long long T = 0ull;
        for (int r = 0; r < 16; r++) {
            unsigned long long m2 = cur;
            for (int off = 16; off; off >>= 1) {
                unsigned long long o = __shfl_xor_sync(0xffffffffu, m2, off);
                if (o > m2) m2 = o;
            }
            T = m2;
            if (cur == m2) cur = 0ull;
        }
        if (tid == 0) s_T = T;
    }
    __syncthreads();

    unsigned long long T = s_T;
#pragma unroll
    for (int j = 0; j < 2; j++) {
        if (my[j] >= T) {
            int p = atomicAdd(&s_nc, 1);
            if (p < SMALLCAP) s_small[p] = my[j];
        }
    }
    __syncthreads();
    int m = s_nc;

    if (m <= SMALLCAP) {
        for (int i = tid; i < m; i += 256) {
            unsigned long long k2 = s_small[i];
            int r = 0;
            for (int p = 0; p < m; p++) r += (s_small[p] > k2);
            if (r < 16) {
                int q = 15 - (int)((k2 >> 17) & 15u);
                int tok = 131071 - (int)(k2 & 0x1FFFFu);
                float comb = funord((unsigned)(k2 >> 32));
                float rr = logprobs[(size_t)(b * 16 + q) * V_ + tok];
                if (tok == V_ - 1) rr -= 1000.0f;
                s_q[r] = q; s_token[r] = tok; s_r[r] = rr;
                out[O2 + b * 16 + r] = comb;
            }
        }
    } else {                                   // fallback: rank all 512
#pragma unroll
        for (int j = 0; j < 2; j++) {
            unsigned long long k2 = my[j];
            int r = 0;
            for (int p = 0; p < 512; p++) r += (s_k2[p] > k2);
            if (r < 16) {
                int q = 15 - (int)((k2 >> 17) & 15u);
                int tok = 131071 - (int)(k2 & 0x1FFFFu);
                float comb = funord((unsigned)(k2 >> 32));
                float rr = logprobs[(size_t)(b * 16 + q) * V_ + tok];
                if (tok == V_ - 1) rr -= 1000.0f;
                s_q[r] = q; s_token[r] = tok; s_r[r] = rr;
                out[O2 + b * 16 + r] = comb;
            }
        }
    }
    __syncthreads();

    // reset diversity-count words for this batch (restores all-zero invariant)
    {
        int vi = s_is64p ? (int)((const long long*)prev)[b * 256 + tid]
                         : ((const int*)prev)[b * 256 + tid];
        g_cnt32[(size_t)b * VPADW + (vi >> 2)] = 0u;   // all writers store 0
    }

    int is64 = g_is64;
    int t = ((const int*)tin)[0];
    for (int idx = tid; idx < T_ * K_; idx += 256) {
        int rowi = idx >> 4, k2i = idx & 15;
        float sv, lv;
        if (rowi == t) {
            sv = (float)s_token[k2i];
            lv = s_r[k2i];
        } else {
            int kk = (rowi < t) ? s_q[k2i] : k2i;
            int off = (b * T_ + rowi) * K_ + kk;
            sv = is64 ? (float)((const long long*)beam_seq)[off]
                      : (float)((const int*)beam_seq)[off];
            lv = beam_lps[off];
        }
        out[O0 + b * (T_ * K_) + idx] = sv;
        out[O1 + b * (T_ * K_) + idx] = lv;
    }

    // fused state gather: 8192 float4/block, deep ILP (load16 -> store16)
#pragma unroll
    for (int r = 0; r < 2; r++) {
        float4 v[16];
#pragma unroll
        for (int j = 0; j < 16; j++) {
            int ii = tid + (r * 16 + j) * 256;
            int rowi = ii >> 7;                  // [0,64): sl*16 + k
            int l = ii & 127;
            int sl = rowi >> 4, k = rowi & 15;
            int q = s_q[k];
            v[j] = ((const float4*)(state + ((((size_t)sl * B_) + b) * K_ + q) * H_))[l];
        }
#pragma unroll
        for (int j = 0; j < 16; j++) {
            int ii = tid + (r * 16 + j) * 256;
            int rowi = ii >> 7;
            int l = ii & 127;
            int sl = rowi >> 4, k = rowi & 15;
            ((float4*)(out + O3 + ((((size_t)sl * B_) + b) * K_ + k) * H_))[l] = v[j];
        }
    }
}

// ---------------------------------------------------------------------------
extern "C" void kernel_launch(void* const* d_in, const int* in_sizes, int n_in,
                              void* d_out, int out_size) {
    const float* logprobs = (const float*)d_in[0];
    const void*  beam_seq = d_in[1];
    const float* beam_lps = (const float*)d_in[2];
    const float* sums     = (const float*)d_in[3];
    const float* state    = (const float*)d_in[4];
    const void*  prev     = d_in[5];
    const void*  tin      = d_in[6];
    float* out = (float*)d_out;

    k_prep<<<B_, 256>>>(prev, beam_seq);
    k_topk<<<NROW * 2, 256>>>(logprobs);
    k_select<<<B_, 256>>>(logprobs, beam_seq, beam_lps, sums, tin, state, prev, out);
}